// round 3
// baseline (speedup 1.0000x reference)
#include <cuda_runtime.h>
#include <cstdint>

#define N_NODES 200000
#define F_IN    128
#define H_DIM   64
#define C_OUT   40
#define MAXDEG  5
#define NBUCKET 6
#define NUM_LAYERS 2

// Scratch (allocation-free rule: __device__ globals)
__device__ float g_h  [(size_t)N_NODES * H_DIM];
__device__ float g_x1 [(size_t)N_NODES * H_DIM];
__device__ float g_agg[(size_t)N_NODES * H_DIM];
__device__ int   g_deg[N_NODES];

// ---------------------------------------------------------------------------
// degree
// ---------------------------------------------------------------------------
__global__ void zero_deg_kernel() {
    int i = blockIdx.x * blockDim.x + threadIdx.x;
    if (i < N_NODES) g_deg[i] = 0;
}

__global__ void deg_kernel(const int* __restrict__ src, const int* __restrict__ dst, int E) {
    for (int e = blockIdx.x * blockDim.x + threadIdx.x; e < E; e += gridDim.x * blockDim.x) {
        int s = src[e], d = dst[e];
        if (s != d) atomicAdd(&g_deg[d], 1);
    }
}

// ---------------------------------------------------------------------------
// h = relu(x @ W1 + b1);  x_first = h.   One warp per node row.
// Wp[k][c] = (W1[k][c], W1[k][c+32]) so each lane computes 2 output cols.
// ---------------------------------------------------------------------------
__global__ void gemm1_kernel(const float* __restrict__ x,
                             const float* __restrict__ W1,
                             const float* __restrict__ b1) {
    __shared__ float2 Wp[F_IN][32];
    __shared__ float2 bp[32];
    int tid = threadIdx.x;
    for (int i = tid; i < F_IN * 32; i += blockDim.x) {
        int k = i >> 5, c = i & 31;
        Wp[k][c] = make_float2(W1[k * H_DIM + c], W1[k * H_DIM + c + 32]);
    }
    if (tid < 32) bp[tid] = make_float2(b1[tid], b1[tid + 32]);
    __syncthreads();

    int lane = tid & 31;
    int node = blockIdx.x * (blockDim.x >> 5) + (tid >> 5);
    if (node >= N_NODES) return;

    float4 xr = *(const float4*)(x + (size_t)node * F_IN + lane * 4);
    float o0 = 0.f, o1 = 0.f;
#pragma unroll
    for (int k = 0; k < F_IN; k++) {
        float mine = ((k & 3) == 0) ? xr.x : ((k & 3) == 1) ? xr.y : ((k & 3) == 2) ? xr.z : xr.w;
        float xv = __shfl_sync(0xffffffffu, mine, k >> 2);
        float2 w = Wp[k][lane];
        o0 = fmaf(xv, w.x, o0);
        o1 = fmaf(xv, w.y, o1);
    }
    float2 b = bp[lane];
    o0 = fmaxf(o0 + b.x, 0.f);
    o1 = fmaxf(o1 + b.y, 0.f);
    size_t base = (size_t)node * H_DIM;
    g_h [base + lane]      = o0;
    g_h [base + lane + 32] = o1;
    g_x1[base + lane]      = o0;
    g_x1[base + lane + 32] = o1;
}

// ---------------------------------------------------------------------------
// agg = h  (self term of aggregation)
// ---------------------------------------------------------------------------
__global__ void copy_h_to_agg_kernel() {
    size_t n4 = (size_t)N_NODES * H_DIM / 4;
    for (size_t i = blockIdx.x * (size_t)blockDim.x + threadIdx.x; i < n4;
         i += (size_t)gridDim.x * blockDim.x)
        ((float4*)g_agg)[i] = ((const float4*)g_h)[i];
}

// ---------------------------------------------------------------------------
// scatter: agg[dst] += h[src] for src != dst.  16 threads per edge,
// each does one float4 via vectorized red.global.add.v4.f32 (sm_90+).
// ---------------------------------------------------------------------------
__global__ void scatter_kernel(const int* __restrict__ src, const int* __restrict__ dst, int E) {
    int lane16  = threadIdx.x & 15;
    int g       = blockIdx.x * (blockDim.x >> 4) + (threadIdx.x >> 4);
    int ngroups = gridDim.x * (blockDim.x >> 4);
    for (int e = g; e < E; e += ngroups) {
        int s = __ldg(src + e);
        int d = __ldg(dst + e);
        if (s == d) continue;
        float4 v = *(const float4*)(g_h + (size_t)s * H_DIM + lane16 * 4);
        float* p = g_agg + (size_t)d * H_DIM + lane16 * 4;
        asm volatile("red.global.add.v4.f32 [%0], {%1, %2, %3, %4};"
                     :: "l"(p), "f"(v.x), "f"(v.y), "f"(v.z), "f"(v.w)
                     : "memory");
    }
}

// ---------------------------------------------------------------------------
// conv: h = agg @ relW[layer][deg] + relb[layer][deg] + fuse[layer] * x_first
// All 6 weight buckets staged in dynamic SMEM as float2 pairs (cols c, c+32).
// One warp per node, grid-stride.
// ---------------------------------------------------------------------------
__global__ void conv_kernel(const float* __restrict__ relW,
                            const float* __restrict__ relb,
                            const float* __restrict__ fuse,
                            int layer) {
    extern __shared__ float2 sm[];
    float2* Wp = sm;                            // [NBUCKET][H_DIM][32]
    float2* bp = sm + NBUCKET * H_DIM * 32;     // [NBUCKET][32]

    const float* W = relW + (size_t)layer * NBUCKET * H_DIM * H_DIM;
    const float* B = relb + (size_t)layer * NBUCKET * H_DIM;

    int tid = threadIdx.x;
    for (int i = tid; i < NBUCKET * H_DIM * 32; i += blockDim.x) {
        int k = i / (H_DIM * 32);
        int r = i - k * (H_DIM * 32);
        int d = r >> 5, c = r & 31;
        const float* Wk = W + ((size_t)k * H_DIM + d) * H_DIM;
        Wp[i] = make_float2(Wk[c], Wk[c + 32]);
    }
    for (int i = tid; i < NBUCKET * 32; i += blockDim.x) {
        int k = i >> 5, c = i & 31;
        bp[i] = make_float2(B[k * H_DIM + c], B[k * H_DIM + c + 32]);
    }
    __syncthreads();

    float fu = fuse[layer];
    int lane  = tid & 31;
    int warps = (gridDim.x * blockDim.x) >> 5;
    for (int node = (blockIdx.x * blockDim.x + tid) >> 5; node < N_NODES; node += warps) {
        float2 ar = *(const float2*)(g_agg + (size_t)node * H_DIM + lane * 2);
        int deg = g_deg[node];
        deg = deg > MAXDEG ? MAXDEG : deg;
        const float2* Wk = Wp + (size_t)deg * H_DIM * 32;
        float o0 = 0.f, o1 = 0.f;
#pragma unroll
        for (int d = 0; d < H_DIM; d++) {
            float av = __shfl_sync(0xffffffffu, (d & 1) ? ar.y : ar.x, d >> 1);
            float2 w = Wk[d * 32 + lane];
            o0 = fmaf(av, w.x, o0);
            o1 = fmaf(av, w.y, o1);
        }
        float2 b = bp[deg * 32 + lane];
        size_t base = (size_t)node * H_DIM;
        g_h[base + lane]      = o0 + b.x + fu * g_x1[base + lane];
        g_h[base + lane + 32] = o1 + b.y + fu * g_x1[base + lane + 32];
    }
}

// ---------------------------------------------------------------------------
// out = log_softmax(h @ Wout + bout).  One warp per node.
// Lane holds cols (lane) and (lane+32, valid lane<8).
// ---------------------------------------------------------------------------
__global__ void out_kernel(const float* __restrict__ Wout,
                           const float* __restrict__ bout,
                           float* __restrict__ out) {
    __shared__ float2 Wp[H_DIM][32];
    __shared__ float2 bp[32];
    int tid = threadIdx.x;
    for (int i = tid; i < H_DIM * 32; i += blockDim.x) {
        int d = i >> 5, c = i & 31;
        float w1 = (c < C_OUT - 32) ? Wout[d * C_OUT + c + 32] : 0.f;
        Wp[d][c] = make_float2(Wout[d * C_OUT + c], w1);
    }
    if (tid < 32) bp[tid] = make_float2(bout[tid], (tid < C_OUT - 32) ? bout[tid + 32] : 0.f);
    __syncthreads();

    int lane = tid & 31;
    int node = blockIdx.x * (blockDim.x >> 5) + (tid >> 5);
    if (node >= N_NODES) return;

    float2 hr = *(const float2*)(g_h + (size_t)node * H_DIM + lane * 2);
    float o0 = 0.f, o1 = 0.f;
#pragma unroll
    for (int d = 0; d < H_DIM; d++) {
        float hv = __shfl_sync(0xffffffffu, (d & 1) ? hr.y : hr.x, d >> 1);
        float2 w = Wp[d][lane];
        o0 = fmaf(hv, w.x, o0);
        o1 = fmaf(hv, w.y, o1);
    }
    float2 b = bp[lane];
    o0 += b.x;
    o1 += b.y;

    // log-softmax over 40 values spread across the warp
    float m = fmaxf(o0, (lane < 8) ? o1 : -3.4e38f);
#pragma unroll
    for (int off = 16; off; off >>= 1) m = fmaxf(m, __shfl_xor_sync(0xffffffffu, m, off));
    float s = expf(o0 - m) + ((lane < 8) ? expf(o1 - m) : 0.f);
#pragma unroll
    for (int off = 16; off; off >>= 1) s += __shfl_xor_sync(0xffffffffu, s, off);
    float lse = logf(s);

    out[(size_t)node * C_OUT + lane] = o0 - m - lse;
    if (lane < 8) out[(size_t)node * C_OUT + 32 + lane] = o1 - m - lse;
}

// ---------------------------------------------------------------------------
// launch
// ---------------------------------------------------------------------------
extern "C" void kernel_launch(void* const* d_in, const int* in_sizes, int n_in,
                              void* d_out, int out_size) {
    const float* x    = (const float*)d_in[0];
    const int*   edge = (const int*)  d_in[1];
    const float* W1   = (const float*)d_in[2];
    const float* b1   = (const float*)d_in[3];
    const float* relW = (const float*)d_in[4];
    const float* relb = (const float*)d_in[5];
    const float* Wout = (const float*)d_in[6];
    const float* bout = (const float*)d_in[7];
    const float* fuse = (const float*)d_in[8];
    float*       out  = (float*)d_out;
    int E = in_sizes[1] / 2;
    const int* srcp = edge;
    const int* dstp = edge + E;

    const int conv_smem = (NBUCKET * H_DIM * 32 + NBUCKET * 32) * (int)sizeof(float2); // 99840 B
    cudaFuncSetAttribute(conv_kernel, cudaFuncAttributeMaxDynamicSharedMemorySize, conv_smem);

    zero_deg_kernel<<<(N_NODES + 255) / 256, 256>>>();
    deg_kernel<<<2048, 256>>>(srcp, dstp, E);
    gemm1_kernel<<<(N_NODES + 7) / 8, 256>>>(x, W1, b1);

    for (int l = 0; l < NUM_LAYERS; l++) {
        copy_h_to_agg_kernel<<<4096, 256>>>();
        scatter_kernel<<<4096, 256>>>(srcp, dstp, E);
        conv_kernel<<<296, 512, conv_smem>>>(relW, relb, fuse, l);
    }

    out_kernel<<<(N_NODES + 7) / 8, 256>>>(Wout, bout, out);
}

// round 5
// speedup vs baseline: 1.3357x; 1.3357x over previous
#include <cuda_runtime.h>
#include <cstdint>

#define N_NODES 200000
#define F_IN    128
#define H_DIM   64
#define C_OUT   40
#define MAXDEG  5
#define NBUCKET 6
#define NUM_LAYERS 2
#define E_MAX   3400000

#define SCAN_ELEMS 1024                   // elements per scan block (256 thr x 4)
#define NUM_SCAN_BLOCKS ((N_NODES + SCAN_ELEMS - 1) / SCAN_ELEMS)   // 196

// ---------------- scratch (__device__ globals: allocation-free rule) --------
__device__ float g_h  [(size_t)N_NODES * H_DIM];
__device__ float g_x1 [(size_t)N_NODES * H_DIM];
__device__ float g_agg[(size_t)N_NODES * H_DIM];
__device__ int   g_cnt[N_NODES];          // raw in-degree (self loops removed)
__device__ int   g_deg[N_NODES];          // clamped degree
__device__ int   g_rowptr[N_NODES + 1];   // CSR row offsets
__device__ int   g_cursor[N_NODES];       // CSR fill cursors
__device__ int   g_esrc[E_MAX];           // CSR column (src node) array
__device__ int   g_blocksums[NUM_SCAN_BLOCKS];
__device__ int   g_bcnt[NBUCKET];
__device__ int   g_bcur[NBUCKET];
__device__ int   g_nodes_sorted[N_NODES]; // node ids grouped by clamped degree

// ---------------------------------------------------------------------------
// setup: counting + scan + CSR fill + degree bucketing
// ---------------------------------------------------------------------------
__global__ void zero_kernel() {
    int i = blockIdx.x * blockDim.x + threadIdx.x;
    if (i < N_NODES) g_cnt[i] = 0;
    if (i < NBUCKET) g_bcnt[i] = 0;
}

__global__ void count_kernel(const int* __restrict__ src, const int* __restrict__ dst, int E) {
    for (int e = blockIdx.x * blockDim.x + threadIdx.x; e < E; e += gridDim.x * blockDim.x) {
        int s = src[e], d = dst[e];
        if (s != d) atomicAdd(&g_cnt[d], 1);
    }
}

// block-local exclusive scan of g_cnt into g_rowptr; block totals to g_blocksums
__global__ void scan_local_kernel() {
    __shared__ int ssum[256];
    int t = threadIdx.x;
    int base = blockIdx.x * SCAN_ELEMS + t * 4;
    int c[4];
    int s = 0;
#pragma unroll
    for (int j = 0; j < 4; j++) {
        int idx = base + j;
        c[j] = (idx < N_NODES) ? g_cnt[idx] : 0;
        s += c[j];
    }
    ssum[t] = s;
    __syncthreads();
#pragma unroll
    for (int off = 1; off < 256; off <<= 1) {
        int v = (t >= off) ? ssum[t - off] : 0;
        __syncthreads();
        ssum[t] += v;
        __syncthreads();
    }
    int p = ssum[t] - s;                    // exclusive prefix for this thread
#pragma unroll
    for (int j = 0; j < 4; j++) {
        int idx = base + j;
        if (idx < N_NODES) g_rowptr[idx] = p;
        p += c[j];
    }
    if (t == 0) g_blocksums[blockIdx.x] = ssum[255];
}

// single-block exclusive scan of the 196 block sums; writes total to rowptr[N]
__global__ void scan_blocksums_kernel() {
    __shared__ int sb[256];
    int t = threadIdx.x;
    int own = (t < NUM_SCAN_BLOCKS) ? g_blocksums[t] : 0;
    sb[t] = own;
    __syncthreads();
#pragma unroll
    for (int off = 1; off < 256; off <<= 1) {
        int v = (t >= off) ? sb[t - off] : 0;
        __syncthreads();
        sb[t] += v;
        __syncthreads();
    }
    if (t < NUM_SCAN_BLOCKS) g_blocksums[t] = sb[t] - own;
    if (t == 0) g_rowptr[N_NODES] = sb[255];
}

// add block offsets; init cursors; clamp degree; count buckets
__global__ void scan_add_kernel() {
    int i = blockIdx.x * blockDim.x + threadIdx.x;
    if (i >= N_NODES) return;
    int r = g_rowptr[i] + g_blocksums[i / SCAN_ELEMS];
    g_rowptr[i] = r;
    g_cursor[i] = r;
    int dg = g_cnt[i];
    dg = dg > MAXDEG ? MAXDEG : dg;
    g_deg[i] = dg;
    atomicAdd(&g_bcnt[dg], 1);
}

__global__ void bucket_offsets_kernel() {
    int off = 0;
#pragma unroll
    for (int k = 0; k < NBUCKET; k++) { g_bcur[k] = off; off += g_bcnt[k]; }
}

__global__ void bucket_fill_kernel() {
    int i = blockIdx.x * blockDim.x + threadIdx.x;
    if (i >= N_NODES) return;
    int pos = atomicAdd(&g_bcur[g_deg[i]], 1);
    g_nodes_sorted[pos] = i;
}

__global__ void csr_fill_kernel(const int* __restrict__ src, const int* __restrict__ dst, int E) {
    for (int e = blockIdx.x * blockDim.x + threadIdx.x; e < E; e += gridDim.x * blockDim.x) {
        int s = src[e], d = dst[e];
        if (s != d) {
            int p = atomicAdd(&g_cursor[d], 1);
            if (p < E_MAX) g_esrc[p] = s;
        }
    }
}

// ---------------------------------------------------------------------------
// gemm1: h = relu(x @ W1 + b1); x_first = h.  4 nodes per warp, persistent.
// Lane l owns output cols (2l, 2l+1).
// ---------------------------------------------------------------------------
__global__ void gemm1_kernel(const float* __restrict__ x,
                             const float* __restrict__ W1,
                             const float* __restrict__ b1) {
    __shared__ float2 Wp[F_IN][32];
    __shared__ float2 bp[32];
    int tid = threadIdx.x;
    for (int i = tid; i < F_IN * 32; i += blockDim.x) {
        int k = i >> 5, c = i & 31;
        Wp[k][c] = make_float2(W1[k * H_DIM + 2 * c], W1[k * H_DIM + 2 * c + 1]);
    }
    if (tid < 32) bp[tid] = make_float2(b1[2 * tid], b1[2 * tid + 1]);
    __syncthreads();

    int lane = tid & 31;
    int warp = (blockIdx.x * blockDim.x + tid) >> 5;
    int nwarps = (gridDim.x * blockDim.x) >> 5;
    const int NG = N_NODES / 4;                 // 50000 groups, exact

    for (int g = warp; g < NG; g += nwarps) {
        int n0 = 4 * g;
        float4 xr[4];
#pragma unroll
        for (int j = 0; j < 4; j++)
            xr[j] = *(const float4*)(x + (size_t)(n0 + j) * F_IN + lane * 4);
        float o0[4] = {0.f, 0.f, 0.f, 0.f}, o1[4] = {0.f, 0.f, 0.f, 0.f};
#pragma unroll
        for (int k = 0; k < F_IN; k++) {
            float2 w = Wp[k][lane];
#pragma unroll
            for (int j = 0; j < 4; j++) {
                float mine = ((k & 3) == 0) ? xr[j].x : ((k & 3) == 1) ? xr[j].y
                           : ((k & 3) == 2) ? xr[j].z : xr[j].w;
                float xv = __shfl_sync(0xffffffffu, mine, k >> 2);
                o0[j] = fmaf(xv, w.x, o0[j]);
                o1[j] = fmaf(xv, w.y, o1[j]);
            }
        }
        float2 b = bp[lane];
#pragma unroll
        for (int j = 0; j < 4; j++) {
            float2 r = make_float2(fmaxf(o0[j] + b.x, 0.f), fmaxf(o1[j] + b.y, 0.f));
            size_t base = (size_t)(n0 + j) * H_DIM + 2 * lane;
            *(float2*)(g_h  + base) = r;
            *(float2*)(g_x1 + base) = r;
        }
    }
}

// ---------------------------------------------------------------------------
// agg: agg[n] = h[n] + sum_{e in CSR row n} h[esrc[e]].  Warp per node.
// ---------------------------------------------------------------------------
__global__ void agg_kernel() {
    int lane = threadIdx.x & 31;
    int node = (blockIdx.x * blockDim.x + threadIdx.x) >> 5;
    if (node >= N_NODES) return;
    int rs = g_rowptr[node], re = g_rowptr[node + 1];
    size_t col = 2 * lane;
    float2 acc = *(const float2*)(g_h + (size_t)node * H_DIM + col);  // self term
    int e = rs;
    for (; e + 4 <= re; e += 4) {
        int s0 = __ldg(g_esrc + e + 0);
        int s1 = __ldg(g_esrc + e + 1);
        int s2 = __ldg(g_esrc + e + 2);
        int s3 = __ldg(g_esrc + e + 3);
        float2 v0 = *(const float2*)(g_h + (size_t)s0 * H_DIM + col);
        float2 v1 = *(const float2*)(g_h + (size_t)s1 * H_DIM + col);
        float2 v2 = *(const float2*)(g_h + (size_t)s2 * H_DIM + col);
        float2 v3 = *(const float2*)(g_h + (size_t)s3 * H_DIM + col);
        acc.x += (v0.x + v1.x) + (v2.x + v3.x);
        acc.y += (v0.y + v1.y) + (v2.y + v3.y);
    }
    for (; e < re; e++) {
        int s0 = __ldg(g_esrc + e);
        float2 v = *(const float2*)(g_h + (size_t)s0 * H_DIM + col);
        acc.x += v.x; acc.y += v.y;
    }
    *(float2*)(g_agg + (size_t)node * H_DIM + col) = acc;
}

// ---------------------------------------------------------------------------
// conv: h = agg @ relW[layer][deg] + relb[layer][deg] + fuse*x_first.
// 4 same-degree nodes per warp (via g_nodes_sorted). Weights in dyn SMEM.
// ---------------------------------------------------------------------------
__global__ void conv_kernel(const float* __restrict__ relW,
                            const float* __restrict__ relb,
                            const float* __restrict__ fuse,
                            int layer) {
    extern __shared__ float2 sm[];
    float2* Wp = sm;                            // [NBUCKET][H_DIM][32]
    float2* bp = sm + NBUCKET * H_DIM * 32;     // [NBUCKET][32]

    const float* W = relW + (size_t)layer * NBUCKET * H_DIM * H_DIM;
    const float* B = relb + (size_t)layer * NBUCKET * H_DIM;

    int tid = threadIdx.x;
    for (int i = tid; i < NBUCKET * H_DIM * 32; i += blockDim.x) {
        int k = i / (H_DIM * 32);
        int r = i - k * (H_DIM * 32);
        int d = r >> 5, c = r & 31;
        const float* Wk = W + ((size_t)k * H_DIM + d) * H_DIM;
        Wp[i] = make_float2(Wk[2 * c], Wk[2 * c + 1]);
    }
    for (int i = tid; i < NBUCKET * 32; i += blockDim.x) {
        int k = i >> 5, c = i & 31;
        bp[i] = make_float2(B[k * H_DIM + 2 * c], B[k * H_DIM + 2 * c + 1]);
    }
    __syncthreads();

    float fu = fuse[layer];
    int lane = tid & 31;
    int warp = (blockIdx.x * blockDim.x + tid) >> 5;
    int nwarps = (gridDim.x * blockDim.x) >> 5;
    const int NG = N_NODES / 4;

    for (int g = warp; g < NG; g += nwarps) {
        int nid[4], dg[4];
#pragma unroll
        for (int j = 0; j < 4; j++) {
            nid[j] = g_nodes_sorted[4 * g + j];
            dg[j]  = g_deg[nid[j]];
        }
        if (dg[0] == dg[1] && dg[1] == dg[2] && dg[2] == dg[3]) {
            // fast path: shared weight bucket
            const float2* Wk = Wp + (size_t)dg[0] * H_DIM * 32;
            float2 a[4];
#pragma unroll
            for (int j = 0; j < 4; j++)
                a[j] = *(const float2*)(g_agg + (size_t)nid[j] * H_DIM + 2 * lane);
            float o0[4] = {0.f, 0.f, 0.f, 0.f}, o1[4] = {0.f, 0.f, 0.f, 0.f};
#pragma unroll
            for (int d = 0; d < H_DIM; d++) {
                float2 w = Wk[d * 32 + lane];
#pragma unroll
                for (int j = 0; j < 4; j++) {
                    float av = __shfl_sync(0xffffffffu, (d & 1) ? a[j].y : a[j].x, d >> 1);
                    o0[j] = fmaf(av, w.x, o0[j]);
                    o1[j] = fmaf(av, w.y, o1[j]);
                }
            }
            float2 b = bp[dg[0] * 32 + lane];
#pragma unroll
            for (int j = 0; j < 4; j++) {
                size_t base = (size_t)nid[j] * H_DIM + 2 * lane;
                float2 x1 = *(const float2*)(g_x1 + base);
                *(float2*)(g_h + base) =
                    make_float2(o0[j] + b.x + fu * x1.x, o1[j] + b.y + fu * x1.y);
            }
        } else {
            // bucket-boundary group (rare): per-node path
            for (int j = 0; j < 4; j++) {
                const float2* Wk = Wp + (size_t)dg[j] * H_DIM * 32;
                float2 a = *(const float2*)(g_agg + (size_t)nid[j] * H_DIM + 2 * lane);
                float o0 = 0.f, o1 = 0.f;
#pragma unroll
                for (int d = 0; d < H_DIM; d++) {
                    float av = __shfl_sync(0xffffffffu, (d & 1) ? a.y : a.x, d >> 1);
                    float2 w = Wk[d * 32 + lane];
                    o0 = fmaf(av, w.x, o0);
                    o1 = fmaf(av, w.y, o1);
                }
                float2 b = bp[dg[j] * 32 + lane];
                size_t base = (size_t)nid[j] * H_DIM + 2 * lane;
                float2 x1 = *(const float2*)(g_x1 + base);
                *(float2*)(g_h + base) =
                    make_float2(o0 + b.x + fu * x1.x, o1 + b.y + fu * x1.y);
            }
        }
    }
}

// ---------------------------------------------------------------------------
// out = log_softmax(h @ Wout + bout). 4 nodes/warp, lane l owns cols (2l,2l+1),
// valid for lane < 20 (C_OUT = 40).
// ---------------------------------------------------------------------------
__global__ void out_kernel(const float* __restrict__ Wout,
                           const float* __restrict__ bout,
                           float* __restrict__ out) {
    __shared__ float2 Wp[H_DIM][32];
    __shared__ float2 bp[32];
    int tid = threadIdx.x;
    for (int i = tid; i < H_DIM * 32; i += blockDim.x) {
        int d = i >> 5, c = i & 31;
        Wp[d][c] = (c < C_OUT / 2)
            ? make_float2(Wout[d * C_OUT + 2 * c], Wout[d * C_OUT + 2 * c + 1])
            : make_float2(0.f, 0.f);
    }
    if (tid < 32)
        bp[tid] = (tid < C_OUT / 2) ? make_float2(bout[2 * tid], bout[2 * tid + 1])
                                    : make_float2(0.f, 0.f);
    __syncthreads();

    int lane = tid & 31;
    int warp = (blockIdx.x * blockDim.x + tid) >> 5;
    int nwarps = (gridDim.x * blockDim.x) >> 5;
    const int NG = N_NODES / 4;

    for (int g = warp; g < NG; g += nwarps) {
        int n0 = 4 * g;
        float2 hr[4];
#pragma unroll
        for (int j = 0; j < 4; j++)
            hr[j] = *(const float2*)(g_h + (size_t)(n0 + j) * H_DIM + 2 * lane);
        float o0[4] = {0.f, 0.f, 0.f, 0.f}, o1[4] = {0.f, 0.f, 0.f, 0.f};
#pragma unroll
        for (int d = 0; d < H_DIM; d++) {
            float2 w = Wp[d][lane];
#pragma unroll
            for (int j = 0; j < 4; j++) {
                float hv = __shfl_sync(0xffffffffu, (d & 1) ? hr[j].y : hr[j].x, d >> 1);
                o0[j] = fmaf(hv, w.x, o0[j]);
                o1[j] = fmaf(hv, w.y, o1[j]);
            }
        }
        float2 b = bp[lane];
        bool valid = (lane < C_OUT / 2);
#pragma unroll
        for (int j = 0; j < 4; j++) {
            float a0 = o0[j] + b.x, a1 = o1[j] + b.y;
            float m = valid ? fmaxf(a0, a1) : -3.4e38f;
#pragma unroll
            for (int off = 16; off; off >>= 1)
                m = fmaxf(m, __shfl_xor_sync(0xffffffffu, m, off));
            float s = valid ? (expf(a0 - m) + expf(a1 - m)) : 0.f;
#pragma unroll
            for (int off = 16; off; off >>= 1)
                s += __shfl_xor_sync(0xffffffffu, s, off);
            float lse = logf(s);
            if (valid)
                *(float2*)(out + (size_t)(n0 + j) * C_OUT + 2 * lane) =
                    make_float2(a0 - m - lse, a1 - m - lse);
        }
    }
}

// ---------------------------------------------------------------------------
// launch
// ---------------------------------------------------------------------------
extern "C" void kernel_launch(void* const* d_in, const int* in_sizes, int n_in,
                              void* d_out, int out_size) {
    const float* x    = (const float*)d_in[0];
    const int*   edge = (const int*)  d_in[1];
    const float* W1   = (const float*)d_in[2];
    const float* b1   = (const float*)d_in[3];
    const float* relW = (const float*)d_in[4];
    const float* relb = (const float*)d_in[5];
    const float* Wout = (const float*)d_in[6];
    const float* bout = (const float*)d_in[7];
    const float* fuse = (const float*)d_in[8];
    float*       out  = (float*)d_out;
    int E = in_sizes[1] / 2;
    const int* srcp = edge;
    const int* dstp = edge + E;

    const int conv_smem = (NBUCKET * H_DIM * 32 + NBUCKET * 32) * (int)sizeof(float2); // 99840 B
    cudaFuncSetAttribute(conv_kernel, cudaFuncAttributeMaxDynamicSharedMemorySize, conv_smem);

    // ---- setup: degree counts, CSR, degree buckets ----
    zero_kernel<<<(N_NODES + 255) / 256, 256>>>();
    count_kernel<<<2048, 256>>>(srcp, dstp, E);
    scan_local_kernel<<<NUM_SCAN_BLOCKS, 256>>>();
    scan_blocksums_kernel<<<1, 256>>>();
    scan_add_kernel<<<(N_NODES + 255) / 256, 256>>>();
    bucket_offsets_kernel<<<1, 1>>>();
    bucket_fill_kernel<<<(N_NODES + 255) / 256, 256>>>();
    csr_fill_kernel<<<2048, 256>>>(srcp, dstp, E);

    // ---- network ----
    gemm1_kernel<<<592, 256>>>(x, W1, b1);
    for (int l = 0; l < NUM_LAYERS; l++) {
        agg_kernel<<<(N_NODES * 32 + 255) / 256, 256>>>();
        conv_kernel<<<296, 512, conv_smem>>>(relW, relb, fuse, l);
    }
    out_kernel<<<592, 256>>>(Wout, bout, out);
}